// round 8
// baseline (speedup 1.0000x reference)
#include <cuda_runtime.h>
#include <cuda_bf16.h>
#include <math.h>
#include <stdint.h>

#define BATCH 32
#define SEQ 196
#define DMODEL 1024
#define HEADS 8
#define DK 128
#define MROWS (BATCH*SEQ)            // 6272

// ---------------- scratch (static device arrays; no allocations) ----------------
__device__ float g_q[MROWS*DMODEL];
__device__ float g_k[MROWS*DMODEL];
__device__ float g_v[MROWS*DMODEL];
__device__ float g_ctx[MROWS*DMODEL];
__device__ float g_vT[(size_t)BATCH*HEADS*DK*SEQ];      // [bh][n][k] transposed V
__device__ float g_logw[(size_t)BATCH*HEADS*SEQ*SEQ];   // geometry log-weights

__constant__ float c_dim[8] = {
    1.0f, 0.4216965034285822f, 0.1778279410038923f, 0.07498942093324558f,
    0.03162277660168379f, 0.013335214321633241f, 0.005623413251903491f,
    0.0023713737056616554f
};

// ============================================================================
// common MMA helpers
// ============================================================================
#define KCHUNK 32
#define GSTRIDE 80                   // bytes per bf16 row: 32 elems * 2B + 16B pad
#define OFF_AHI 0
#define OFF_ALO (128*GSTRIDE)
#define OFF_BHI (2*128*GSTRIDE)
#define OFF_BLO (3*128*GSTRIDE)
#define BUFSZ   (4*128*GSTRIDE)      // 40960
#define SMEMSZ  (2*BUFSZ)            // 81920 (projection kernels)

#define SSTRIDE 224                  // fused kernel S row stride (floats)
#define SMEM_FUSED (2*BUFSZ + 128*SSTRIDE*4)   // 81920 + 114688 = 196608

__device__ __forceinline__ uint32_t smem_u32(const void* p) {
    uint32_t a;
    asm("{ .reg .u64 t; cvta.to.shared.u64 t, %1; cvt.u32.u64 %0, t; }" : "=r"(a) : "l"(p));
    return a;
}

__device__ __forceinline__ void ldsm4(uint32_t r[4], uint32_t addr) {
    asm volatile("ldmatrix.sync.aligned.m8n8.x4.shared.b16 {%0,%1,%2,%3}, [%4];"
        : "=r"(r[0]), "=r"(r[1]), "=r"(r[2]), "=r"(r[3]) : "r"(addr));
}

__device__ __forceinline__ void mma16816(float d[4], const uint32_t a[4], const uint32_t b[2]) {
    asm volatile("mma.sync.aligned.m16n8k16.row.col.f32.bf16.bf16.f32 "
        "{%0,%1,%2,%3}, {%4,%5,%6,%7}, {%8,%9}, {%0,%1,%2,%3};"
        : "+f"(d[0]), "+f"(d[1]), "+f"(d[2]), "+f"(d[3])
        : "r"(a[0]), "r"(a[1]), "r"(a[2]), "r"(a[3]), "r"(b[0]), "r"(b[1]));
}

__device__ __forceinline__ void split4(float4 v, uint2& hi, uint2& lo) {
    __nv_bfloat162 h0 = __float22bfloat162_rn(make_float2(v.x, v.y));
    __nv_bfloat162 h1 = __float22bfloat162_rn(make_float2(v.z, v.w));
    uint32_t u0 = *(uint32_t*)&h0, u1 = *(uint32_t*)&h1;
    float hx = __uint_as_float(u0 << 16);
    float hy = __uint_as_float(u0 & 0xFFFF0000u);
    float hz = __uint_as_float(u1 << 16);
    float hw = __uint_as_float(u1 & 0xFFFF0000u);
    __nv_bfloat162 l0 = __float22bfloat162_rn(make_float2(v.x - hx, v.y - hy));
    __nv_bfloat162 l1 = __float22bfloat162_rn(make_float2(v.z - hz, v.w - hw));
    hi = make_uint2(u0, u1);
    lo = make_uint2(*(uint32_t*)&l0, *(uint32_t*)&l1);
}

// ---- 512-thread staging: 2 float4 per thread (A 128x32 + B 128x32) ----
__device__ __forceinline__ void stage_store512(char* bp, const float4 pa[2],
                                               const float4 pb[2], int r_ld, int c4)
{
#pragma unroll
    for (int it = 0; it < 2; ++it) {
        uint32_t off = (uint32_t)(it * 64 + r_ld) * GSTRIDE + c4 * 8;
        uint2 hi, lo;
        split4(pa[it], hi, lo);
        *(uint2*)(bp + OFF_AHI + off) = hi;
        *(uint2*)(bp + OFF_ALO + off) = lo;
        split4(pb[it], hi, lo);
        *(uint2*)(bp + OFF_BHI + off) = hi;
        *(uint2*)(bp + OFF_BLO + off) = lo;
    }
}

// one 32-K chunk, 16-warp layout (warp tile 32x32)
__device__ __forceinline__ void mma_chunk512(uint32_t base, float acc[2][4][4],
                                             int warp_m, int warp_n, int sub, int i8)
{
#pragma unroll
    for (int ks = 0; ks < 2; ++ks) {
        const int kofs = ks * 16;
        uint32_t aHi[2][4], aLo[2][4];
#pragma unroll
        for (int mt = 0; mt < 2; ++mt) {
            int row = warp_m * 32 + mt * 16 + (sub & 1) * 8 + i8;
            int col = kofs + (sub >> 1) * 8;
            uint32_t ad = base + OFF_AHI + (uint32_t)row * GSTRIDE + col * 2;
            ldsm4(aHi[mt], ad);
            ldsm4(aLo[mt], ad + (OFF_ALO - OFF_AHI));
        }
#pragma unroll
        for (int ntp = 0; ntp < 2; ++ntp) {
            int nr = warp_n * 32 + ntp * 16 + (sub >> 1) * 8 + i8;
            int nc = kofs + (sub & 1) * 8;
            uint32_t bd = base + OFF_BHI + (uint32_t)nr * GSTRIDE + nc * 2;
            uint32_t bHi[4], bLo[4];
            ldsm4(bHi, bd);
            ldsm4(bLo, bd + (OFF_BLO - OFF_BHI));
#pragma unroll
            for (int mt = 0; mt < 2; ++mt) {
#pragma unroll
                for (int nh = 0; nh < 2; ++nh) {
                    float* d = acc[mt][ntp * 2 + nh];
                    mma16816(d, aHi[mt], &bHi[nh * 2]);
                    mma16816(d, aLo[mt], &bHi[nh * 2]);
                    mma16816(d, aHi[mt], &bLo[nh * 2]);
                }
            }
        }
    }
}

// ============================================================================
// projection GEMM (exact tiles): Y[M,1024] = X[M,1024] @ W[1024,1024]^T + bias
// 512 threads, 16 warps (4m x 4n), warp tile 32x32, CTA tile 128x128.
// ============================================================================
#define NCHUNK (DMODEL / KCHUNK)     // 32

__device__ __forceinline__ void bf16x3_gemm(const float* __restrict__ X,
                                            const float* __restrict__ W,
                                            const float* __restrict__ bias,
                                            float* __restrict__ Y)
{
    extern __shared__ __align__(16) char sm[];
    const uint32_t smb = smem_u32(sm);
    const int tid = threadIdx.x;
    const int lane = tid & 31, w = tid >> 5;     // w: 0..15
    const int warp_m = w & 3, warp_n = w >> 2;
    const int m0 = blockIdx.y * 128, n0 = blockIdx.x * 128;
    const int r_ld = tid >> 3, c4 = tid & 7;     // r_ld: 0..63
    const int sub = lane >> 3, i8 = lane & 7;

    float acc[2][4][4];
#pragma unroll
    for (int mt = 0; mt < 2; mt++)
#pragma unroll
        for (int nt = 0; nt < 4; nt++)
#pragma unroll
            for (int e = 0; e < 4; e++) acc[mt][nt][e] = 0.f;

    float4 pa[2], pb[2];

    {
        const float* Ag = X + c4 * 4;
        const float* Bg = W + c4 * 4;
#pragma unroll
        for (int it = 0; it < 2; ++it) {
            pa[it] = *(const float4*)(Ag + (size_t)(m0 + it * 64 + r_ld) * DMODEL);
            pb[it] = *(const float4*)(Bg + (size_t)(n0 + it * 64 + r_ld) * DMODEL);
        }
        stage_store512(sm, pa, pb, r_ld, c4);
    }
    __syncthreads();

    for (int c = 0; c < NCHUNK; ++c) {
        if (c + 1 < NCHUNK) {
            const int kc = (c + 1) * KCHUNK;
            const float* Ag = X + kc + c4 * 4;
            const float* Bg = W + kc + c4 * 4;
#pragma unroll
            for (int it = 0; it < 2; ++it) {
                pa[it] = *(const float4*)(Ag + (size_t)(m0 + it * 64 + r_ld) * DMODEL);
                pb[it] = *(const float4*)(Bg + (size_t)(n0 + it * 64 + r_ld) * DMODEL);
            }
        }
        mma_chunk512(smb + (uint32_t)(c & 1) * BUFSZ, acc, warp_m, warp_n, sub, i8);
        if (c + 1 < NCHUNK)
            stage_store512(sm + ((c + 1) & 1) * BUFSZ, pa, pb, r_ld, c4);
        __syncthreads();
    }

    const int g = lane >> 2, t4 = lane & 3;
#pragma unroll
    for (int mt = 0; mt < 2; ++mt) {
        int row = m0 + warp_m * 32 + mt * 16 + g;
#pragma unroll
        for (int nt = 0; nt < 4; ++nt) {
            int col = n0 + warp_n * 32 + nt * 8 + 2 * t4;
            float b0 = bias[col], b1 = bias[col + 1];
            float* d = acc[mt][nt];
            *(float2*)&Y[(size_t)row * DMODEL + col] = make_float2(d[0] + b0, d[1] + b1);
            *(float2*)&Y[(size_t)(row + 8) * DMODEL + col] = make_float2(d[2] + b0, d[3] + b1);
        }
    }
}

__global__ void __launch_bounds__(512, 1)
qkv_mma(const float* __restrict__ xq, const float* __restrict__ xk,
        const float* __restrict__ xv,
        const float* __restrict__ wq, const float* __restrict__ wk,
        const float* __restrict__ wv,
        const float* __restrict__ bq, const float* __restrict__ bk,
        const float* __restrict__ bv)
{
    int z = blockIdx.z;
    const float* X = (z == 0) ? xq : (z == 1) ? xk : xv;
    const float* W = (z == 0) ? wq : (z == 1) ? wk : wv;
    const float* bias = (z == 0) ? bq : (z == 1) ? bk : bv;
    float* Y = (z == 0) ? g_q : (z == 1) ? g_k : g_v;
    bf16x3_gemm(X, W, bias, Y);
}

__global__ void __launch_bounds__(512, 1)
out_mma(const float* __restrict__ Wo, const float* __restrict__ bo,
        float* __restrict__ Y)
{
    bf16x3_gemm(g_ctx, Wo, bo, Y);
}

// ============================================================================
// fused attention, 512 threads / 16 warps, warp tile 32x32 (4x4 warp grid)
//   A) S = Q K^T * scale + logw     -> SMEM  (bf16x3 MMA, two 128x128 halves)
//   B) softmax rows of S in SMEM    (+ zero pad cols 196..223)
//   C) ctx = P @ V^T                (A staged from SMEM, B from g_vT)
// ============================================================================
__global__ void __launch_bounds__(512, 1)
fused_attn()
{
    extern __shared__ __align__(16) char sm[];
    const uint32_t smb = smem_u32(sm);
    float* sS = (float*)(sm + 2 * BUFSZ);        // 128 x SSTRIDE fp32

    const int bh = blockIdx.y;
    const int b = bh >> 3, h = bh & 7;
    const int m0 = blockIdx.x * 128;
    const float* Q  = g_q + (size_t)b * SEQ * DMODEL + h * DK;
    const float* Kp = g_k + (size_t)b * SEQ * DMODEL + h * DK;
    const float* LW = g_logw + (size_t)bh * SEQ * SEQ;
    const float* Vt = g_vT + (size_t)bh * DK * SEQ;

    const int tid = threadIdx.x;
    const int lane = tid & 31, w = tid >> 5;     // w: 0..15
    const int warp_m = w & 3, warp_n = w >> 2;   // 4 x 4 warp grid
    const int r_ld = tid >> 3, c4 = tid & 7;     // r_ld: 0..63
    const int sub = lane >> 3, i8 = lane & 7;
    const int g = lane >> 2, t4 = lane & 3;
    const float4 z4 = make_float4(0.f, 0.f, 0.f, 0.f);

    float acc[2][4][4];
    float4 pa[2], pb[2];

    // ======== Phase A: S = Q K^T * scale + logw (two 128x128 n-halves) ========
    const float scale = 0.08838834764831845f;   // 1/sqrt(128)
#pragma unroll 1
    for (int nt2 = 0; nt2 < 2; ++nt2) {
        const int n0 = nt2 * 128;
#pragma unroll
        for (int mt = 0; mt < 2; mt++)
#pragma unroll
            for (int nt = 0; nt < 4; nt++)
#pragma unroll
                for (int e = 0; e < 4; e++) acc[mt][nt][e] = 0.f;

        {
            int gk = c4 * 4;
#pragma unroll
            for (int it = 0; it < 2; ++it) {
                int am = m0 + it * 64 + r_ld;
                int bn = n0 + it * 64 + r_ld;
                pa[it] = (am < SEQ) ? *(const float4*)(Q + (size_t)am * DMODEL + gk) : z4;
                pb[it] = (bn < SEQ) ? *(const float4*)(Kp + (size_t)bn * DMODEL + gk) : z4;
            }
            stage_store512(sm, pa, pb, r_ld, c4);
        }
        __syncthreads();

        for (int c = 0; c < 4; ++c) {          // DK=128 -> 4 chunks
            if (c + 1 < 4) {
                int gk = (c + 1) * KCHUNK + c4 * 4;
#pragma unroll
                for (int it = 0; it < 2; ++it) {
                    int am = m0 + it * 64 + r_ld;
                    int bn = n0 + it * 64 + r_ld;
                    pa[it] = (am < SEQ) ? *(const float4*)(Q + (size_t)am * DMODEL + gk) : z4;
                    pb[it] = (bn < SEQ) ? *(const float4*)(Kp + (size_t)bn * DMODEL + gk) : z4;
                }
            }
            mma_chunk512(smb + (uint32_t)(c & 1) * BUFSZ, acc, warp_m, warp_n, sub, i8);
            if (c + 1 < 4)
                stage_store512(sm + ((c + 1) & 1) * BUFSZ, pa, pb, r_ld, c4);
            __syncthreads();
        }

        // epilogue -> sS (+logw)
#pragma unroll
        for (int mt = 0; mt < 2; ++mt) {
            int rl = warp_m * 32 + mt * 16 + g;        // local row 0..127
            int m = m0 + rl;
#pragma unroll
            for (int nt = 0; nt < 4; ++nt) {
                int col = n0 + warp_n * 32 + nt * 8 + 2 * t4;
                float* d = acc[mt][nt];
                if (col < SEQ) {
                    bool mok = (m < SEQ);
                    float l0 = mok ? LW[(size_t)m * SEQ + col] : 0.f;
                    float l1 = mok ? LW[(size_t)m * SEQ + col + 1] : 0.f;
                    *(float2*)&sS[(size_t)rl * SSTRIDE + col] =
                        make_float2(fmaf(d[0], scale, l0), fmaf(d[1], scale, l1));
                    bool m8 = (m + 8 < SEQ);
                    float l2 = m8 ? LW[(size_t)(m + 8) * SEQ + col] : 0.f;
                    float l3 = m8 ? LW[(size_t)(m + 8) * SEQ + col + 1] : 0.f;
                    *(float2*)&sS[(size_t)(rl + 8) * SSTRIDE + col] =
                        make_float2(fmaf(d[2], scale, l2), fmaf(d[3], scale, l3));
                }
            }
        }
        __syncthreads();
    }

    // ======== Phase B: softmax rows in SMEM (16 warps x 8 rows) ========
    {
#pragma unroll 1
        for (int j = 0; j < 8; ++j) {
            int r = w * 8 + j;
            float* row = sS + (size_t)r * SSTRIDE;
            float x[7];
            float mx = -1e30f;
#pragma unroll
            for (int i = 0; i < 7; ++i) {
                int cidx = lane + i * 32;
                x[i] = (cidx < SEQ) ? row[cidx] : -1e30f;
                mx = fmaxf(mx, x[i]);
            }
#pragma unroll
            for (int o = 16; o > 0; o >>= 1) mx = fmaxf(mx, __shfl_xor_sync(0xffffffffu, mx, o));
            float sum = 0.f;
#pragma unroll
            for (int i = 0; i < 7; ++i) {
                x[i] = expf(x[i] - mx);
                sum += x[i];
            }
#pragma unroll
            for (int o = 16; o > 0; o >>= 1) sum += __shfl_xor_sync(0xffffffffu, sum, o);
            float inv = 1.0f / sum;
#pragma unroll
            for (int i = 0; i < 7; ++i) {
                int cidx = lane + i * 32;
                if (cidx < SEQ) row[cidx] = x[i] * inv;
            }
            if (lane < 28) row[SEQ + lane] = 0.f;     // zero pad cols 196..223
        }
    }
    __syncthreads();

    // ======== Phase C: ctx = P @ V^T (output 128x128) ========
#pragma unroll
    for (int mt = 0; mt < 2; mt++)
#pragma unroll
        for (int nt = 0; nt < 4; nt++)
#pragma unroll
            for (int e = 0; e < 4; e++) acc[mt][nt][e] = 0.f;

    const int nchunkC = 7;                        // ceil(196/32)
    {
        int gk = c4 * 4;
#pragma unroll
        for (int it = 0; it < 2; ++it) {
            int rr = it * 64 + r_ld;
            pa[it] = *(const float4*)(sS + (size_t)rr * SSTRIDE + gk);
            pb[it] = *(const float4*)(Vt + (size_t)rr * SEQ + gk);
        }
        stage_store512(sm, pa, pb, r_ld, c4);
    }
    __syncthreads();

    for (int c = 0; c < nchunkC; ++c) {
        if (c + 1 < nchunkC) {
            int gk = (c + 1) * KCHUNK + c4 * 4;
            bool kok = gk < SEQ;
#pragma unroll
            for (int it = 0; it < 2; ++it) {
                int rr = it * 64 + r_ld;
                pa[it] = *(const float4*)(sS + (size_t)rr * SSTRIDE + gk);   // pad zeroed
                pb[it] = kok ? *(const float4*)(Vt + (size_t)rr * SEQ + gk) : z4;
            }
        }
        mma_chunk512(smb + (uint32_t)(c & 1) * BUFSZ, acc, warp_m, warp_n, sub, i8);
        if (c + 1 < nchunkC)
            stage_store512(sm + ((c + 1) & 1) * BUFSZ, pa, pb, r_ld, c4);
        __syncthreads();
    }

    // epilogue -> g_ctx
    float* C = g_ctx + (size_t)b * SEQ * DMODEL + h * DK;
#pragma unroll
    for (int mt = 0; mt < 2; ++mt) {
        int m = m0 + warp_m * 32 + mt * 16 + g;
#pragma unroll
        for (int nt = 0; nt < 4; ++nt) {
            int col = warp_n * 32 + nt * 8 + 2 * t4;
            float* d = acc[mt][nt];
            if (m < SEQ)
                *(float2*)(C + (size_t)m * DMODEL + col) = make_float2(d[0], d[1]);
            if (m + 8 < SEQ)
                *(float2*)(C + (size_t)(m + 8) * DMODEL + col) = make_float2(d[2], d[3]);
        }
    }
}

// ---------------- V transpose: g_vT[bh][n][k] = g_v[b][k][h*DK+n] ----------------
__global__ void vT_kernel()
{
    __shared__ float t[32][33];
    int bh = blockIdx.z;
    int b = bh >> 3, h = bh & 7;
    int k0 = blockIdx.x * 32, n0 = blockIdx.y * 32;
    int tx = threadIdx.x, ty = threadIdx.y;   // 32 x 8
#pragma unroll
    for (int j = 0; j < 4; ++j) {
        int k = k0 + ty + j * 8;
        t[ty + j * 8][tx] = (k < SEQ)
            ? g_v[((size_t)b * SEQ + k) * DMODEL + h * DK + n0 + tx] : 0.f;
    }
    __syncthreads();
#pragma unroll
    for (int j = 0; j < 4; ++j) {
        int n = n0 + ty + j * 8;
        int k = k0 + tx;
        if (k < SEQ)
            g_vT[(size_t)bh * DK * SEQ + (size_t)n * SEQ + k] = t[tx][ty + j * 8];
    }
}

// ---------------- geometry embedding -> logw[b,h,n,m] ----------------
__global__ void logw_kernel(const float* __restrict__ boxes,
                            const float* __restrict__ WGw,
                            const float* __restrict__ WGb)
{
    __shared__ float sW[8][64];
    __shared__ float sB[8];
    __shared__ float sbn[4];
    int t = threadIdx.x;
    int b = blockIdx.x / SEQ;
    int n = blockIdx.x % SEQ;

    for (int i = t; i < 512; i += blockDim.x) sW[i >> 6][i & 63] = WGw[i];
    if (t < 8) sB[t] = WGb[t];
    if (t == 0) {
        const float* bp = boxes + ((size_t)b * SEQ + n) * 4;
        float xmn = bp[0], ymn = bp[1], xmx = bp[2], ymx = bp[3];
        sbn[0] = (xmn + xmx) * 0.5f;
        sbn[1] = (ymn + ymx) * 0.5f;
        sbn[2] = (xmx - xmn) + 1.0f;
        sbn[3] = (ymx - ymn) + 1.0f;
    }
    __syncthreads();

    int m = t;
    if (m >= SEQ) return;

    const float* bm = boxes + ((size_t)b * SEQ + m) * 4;
    float xmn = bm[0], ymn = bm[1], xmx = bm[2], ymx = bm[3];
    float cxm = (xmn + xmx) * 0.5f, cym = (ymn + ymx) * 0.5f;
    float wm = (xmx - xmn) + 1.0f, hm = (ymx - ymn) + 1.0f;
    float cxn = sbn[0], cyn = sbn[1], wn = sbn[2], hn = sbn[3];

    float pos[4];
    pos[0] = logf(fmaxf(fabsf((cxn - cxm) / wn), 1e-3f));
    pos[1] = logf(fmaxf(fabsf((cyn - cym) / hn), 1e-3f));
    pos[2] = logf(wn / wm);
    pos[3] = logf(hn / hm);

    float acc[8];
#pragma unroll
    for (int h = 0; h < 8; h++) acc[h] = sB[h];

#pragma unroll
    for (int c = 0; c < 4; c++) {
        float p = 100.0f * pos[c];
#pragma unroll
        for (int j = 0; j < 8; j++) {
            float s, co;
            __sincosf(p * c_dim[j], &s, &co);
            int f = c * 8 + j;
#pragma unroll
            for (int h = 0; h < 8; h++)
                acc[h] += s * sW[h][f] + co * sW[h][f + 32];
        }
    }

    size_t base = ((size_t)b * HEADS) * SEQ * SEQ + (size_t)n * SEQ + m;
#pragma unroll
    for (int h = 0; h < 8; h++) {
        float wg = fmaxf(acc[h], 1e-6f);
        g_logw[base + (size_t)h * SEQ * SEQ] = logf(wg);
    }
}

// ---------------- launch ----------------
extern "C" void kernel_launch(void* const* d_in, const int* in_sizes, int n_in,
                              void* d_out, int out_size)
{
    const float* xq  = (const float*)d_in[0];
    const float* xk  = (const float*)d_in[1];
    const float* xv  = (const float*)d_in[2];
    const float* box = (const float*)d_in[3];
    const float* Wq  = (const float*)d_in[4];
    const float* bq  = (const float*)d_in[5];
    const float* Wk  = (const float*)d_in[6];
    const float* bk  = (const float*)d_in[7];
    const float* Wv  = (const float*)d_in[8];
    const float* bv  = (const float*)d_in[9];
    const float* Wo  = (const float*)d_in[10];
    const float* bo  = (const float*)d_in[11];
    const float* WGw = (const float*)d_in[12];
    const float* WGb = (const float*)d_in[13];
    float* out = (float*)d_out;

    cudaFuncSetAttribute(qkv_mma,    cudaFuncAttributeMaxDynamicSharedMemorySize, SMEMSZ);
    cudaFuncSetAttribute(out_mma,    cudaFuncAttributeMaxDynamicSharedMemorySize, SMEMSZ);
    cudaFuncSetAttribute(fused_attn, cudaFuncAttributeMaxDynamicSharedMemorySize, SMEM_FUSED);

    // 1) Q/K/V projections (bf16x3 MMA, 512 threads)
    qkv_mma<<<dim3(DMODEL / 128, MROWS / 128, 3), 512, SMEMSZ>>>(
        xq, xk, xv, Wq, Wk, Wv, bq, bk, bv);

    // 2) transpose V per head
    vT_kernel<<<dim3(7, 4, BATCH * HEADS), dim3(32, 8)>>>();

    // 3) geometry relation log-weights
    logw_kernel<<<BATCH * SEQ, 224>>>(box, WGw, WGb);

    // 4) fused: S = QK^T/sqrt(dk)+logw -> softmax -> P@V  (512 threads)
    fused_attn<<<dim3(2, BATCH * HEADS), 512, SMEM_FUSED>>>();

    // 5) output projection into d_out (512 threads)
    out_mma<<<dim3(DMODEL / 128, MROWS / 128, 1), 512, SMEMSZ>>>(Wo, bo, out);
}

// round 9
// speedup vs baseline: 1.0712x; 1.0712x over previous
#include <cuda_runtime.h>
#include <cuda_bf16.h>
#include <math.h>
#include <stdint.h>

#define BATCH 32
#define SEQ 196
#define DMODEL 1024
#define HEADS 8
#define DK 128
#define MROWS (BATCH*SEQ)            // 6272

// ---------------- scratch (static device arrays; no allocations) ----------------
__device__ float g_q[MROWS*DMODEL];
__device__ float g_k[MROWS*DMODEL];
__device__ float g_v[MROWS*DMODEL];
__device__ float g_ctx[MROWS*DMODEL];
__device__ float g_vT[(size_t)BATCH*HEADS*DK*SEQ];      // [bh][n][k] transposed V
__device__ float g_logw[(size_t)BATCH*HEADS*SEQ*SEQ];   // geometry log-weights

__constant__ float c_dim[8] = {
    1.0f, 0.4216965034285822f, 0.1778279410038923f, 0.07498942093324558f,
    0.03162277660168379f, 0.013335214321633241f, 0.005623413251903491f,
    0.0023713737056616554f
};

// ============================================================================
// common MMA helpers
// ============================================================================
#define KCHUNK 32
#define GSTRIDE 80                   // bytes per bf16 row: 32 elems * 2B + 16B pad
#define OFF_AHI 0
#define OFF_ALO (128*GSTRIDE)
#define OFF_BHI (2*128*GSTRIDE)
#define OFF_BLO (3*128*GSTRIDE)
#define BUFSZ   (4*128*GSTRIDE)      // 40960
#define SMEMSZ  (2*BUFSZ)            // 81920 (projection kernels)

#define SSTRIDE 224                  // fused kernel S row stride (floats)
#define SMEM_FUSED (2*BUFSZ + 128*SSTRIDE*4)   // 81920 + 114688 = 196608

__device__ __forceinline__ uint32_t smem_u32(const void* p) {
    uint32_t a;
    asm("{ .reg .u64 t; cvta.to.shared.u64 t, %1; cvt.u32.u64 %0, t; }" : "=r"(a) : "l"(p));
    return a;
}

__device__ __forceinline__ void ldsm4(uint32_t r[4], uint32_t addr) {
    asm volatile("ldmatrix.sync.aligned.m8n8.x4.shared.b16 {%0,%1,%2,%3}, [%4];"
        : "=r"(r[0]), "=r"(r[1]), "=r"(r[2]), "=r"(r[3]) : "r"(addr));
}

__device__ __forceinline__ void mma16816(float d[4], const uint32_t a[4], const uint32_t b[2]) {
    asm volatile("mma.sync.aligned.m16n8k16.row.col.f32.bf16.bf16.f32 "
        "{%0,%1,%2,%3}, {%4,%5,%6,%7}, {%8,%9}, {%0,%1,%2,%3};"
        : "+f"(d[0]), "+f"(d[1]), "+f"(d[2]), "+f"(d[3])
        : "r"(a[0]), "r"(a[1]), "r"(a[2]), "r"(a[3]), "r"(b[0]), "r"(b[1]));
}

__device__ __forceinline__ void split4(float4 v, uint2& hi, uint2& lo) {
    __nv_bfloat162 h0 = __float22bfloat162_rn(make_float2(v.x, v.y));
    __nv_bfloat162 h1 = __float22bfloat162_rn(make_float2(v.z, v.w));
    uint32_t u0 = *(uint32_t*)&h0, u1 = *(uint32_t*)&h1;
    float hx = __uint_as_float(u0 << 16);
    float hy = __uint_as_float(u0 & 0xFFFF0000u);
    float hz = __uint_as_float(u1 << 16);
    float hw = __uint_as_float(u1 & 0xFFFF0000u);
    __nv_bfloat162 l0 = __float22bfloat162_rn(make_float2(v.x - hx, v.y - hy));
    __nv_bfloat162 l1 = __float22bfloat162_rn(make_float2(v.z - hz, v.w - hw));
    hi = make_uint2(u0, u1);
    lo = make_uint2(*(uint32_t*)&l0, *(uint32_t*)&l1);
}

// ---- 256-thread staging (projection kernels): 4 float4 per thread ----
__device__ __forceinline__ void stage_store(char* bp, const float4 pa[4],
                                            const float4 pb[4], int r_ld, int c4)
{
#pragma unroll
    for (int it = 0; it < 4; ++it) {
        uint32_t off = (uint32_t)(it * 32 + r_ld) * GSTRIDE + c4 * 8;
        uint2 hi, lo;
        split4(pa[it], hi, lo);
        *(uint2*)(bp + OFF_AHI + off) = hi;
        *(uint2*)(bp + OFF_ALO + off) = lo;
        split4(pb[it], hi, lo);
        *(uint2*)(bp + OFF_BHI + off) = hi;
        *(uint2*)(bp + OFF_BLO + off) = lo;
    }
}

// one 32-K chunk, 8-warp layout (warp tile 32x64) — projections
__device__ __forceinline__ void mma_chunk(uint32_t base, float acc[2][8][4],
                                          int warp_m, int warp_n, int sub, int i8)
{
#pragma unroll
    for (int ks = 0; ks < 2; ++ks) {
        const int kofs = ks * 16;
        uint32_t aHi[2][4], aLo[2][4];
#pragma unroll
        for (int mt = 0; mt < 2; ++mt) {
            int row = warp_m * 32 + mt * 16 + (sub & 1) * 8 + i8;
            int col = kofs + (sub >> 1) * 8;
            uint32_t ad = base + OFF_AHI + (uint32_t)row * GSTRIDE + col * 2;
            ldsm4(aHi[mt], ad);
            ldsm4(aLo[mt], ad + (OFF_ALO - OFF_AHI));
        }
#pragma unroll
        for (int ntp = 0; ntp < 4; ++ntp) {
            int nr = warp_n * 64 + ntp * 16 + (sub >> 1) * 8 + i8;
            int nc = kofs + (sub & 1) * 8;
            uint32_t bd = base + OFF_BHI + (uint32_t)nr * GSTRIDE + nc * 2;
            uint32_t bHi[4], bLo[4];
            ldsm4(bHi, bd);
            ldsm4(bLo, bd + (OFF_BLO - OFF_BHI));
#pragma unroll
            for (int mt = 0; mt < 2; ++mt) {
#pragma unroll
                for (int nh = 0; nh < 2; ++nh) {
                    float* d = acc[mt][ntp * 2 + nh];
                    mma16816(d, aHi[mt], &bHi[nh * 2]);
                    mma16816(d, aLo[mt], &bHi[nh * 2]);
                    mma16816(d, aHi[mt], &bLo[nh * 2]);
                }
            }
        }
    }
}

// ============================================================================
// projection GEMM (exact tiles): Y[M,1024] = X[M,1024] @ W[1024,1024]^T + bias
// 256 threads, 8 warps (4m x 2n), warp tile 32x64 — R7 proven config.
// ============================================================================
#define NCHUNK (DMODEL / KCHUNK)     // 32

__device__ __forceinline__ void bf16x3_gemm(const float* __restrict__ X,
                                            const float* __restrict__ W,
                                            const float* __restrict__ bias,
                                            float* __restrict__ Y)
{
    extern __shared__ __align__(16) char sm[];
    const uint32_t smb = smem_u32(sm);
    const int tid = threadIdx.x;
    const int lane = tid & 31, w = tid >> 5;
    const int warp_m = w & 3, warp_n = w >> 2;
    const int m0 = blockIdx.y * 128, n0 = blockIdx.x * 128;
    const int r_ld = tid >> 3, c4 = tid & 7;
    const int sub = lane >> 3, i8 = lane & 7;

    float acc[2][8][4];
#pragma unroll
    for (int mt = 0; mt < 2; mt++)
#pragma unroll
        for (int nt = 0; nt < 8; nt++)
#pragma unroll
            for (int e = 0; e < 4; e++) acc[mt][nt][e] = 0.f;

    float4 pa[4], pb[4];

    {
        const float* Ag = X + c4 * 4;
        const float* Bg = W + c4 * 4;
#pragma unroll
        for (int it = 0; it < 4; ++it) {
            pa[it] = *(const float4*)(Ag + (size_t)(m0 + it * 32 + r_ld) * DMODEL);
            pb[it] = *(const float4*)(Bg + (size_t)(n0 + it * 32 + r_ld) * DMODEL);
        }
        stage_store(sm, pa, pb, r_ld, c4);
    }
    __syncthreads();

    for (int c = 0; c < NCHUNK; ++c) {
        if (c + 1 < NCHUNK) {
            const int kc = (c + 1) * KCHUNK;
            const float* Ag = X + kc + c4 * 4;
            const float* Bg = W + kc + c4 * 4;
#pragma unroll
            for (int it = 0; it < 4; ++it) {
                pa[it] = *(const float4*)(Ag + (size_t)(m0 + it * 32 + r_ld) * DMODEL);
                pb[it] = *(const float4*)(Bg + (size_t)(n0 + it * 32 + r_ld) * DMODEL);
            }
        }
        mma_chunk(smb + (uint32_t)(c & 1) * BUFSZ, acc, warp_m, warp_n, sub, i8);
        if (c + 1 < NCHUNK)
            stage_store(sm + ((c + 1) & 1) * BUFSZ, pa, pb, r_ld, c4);
        __syncthreads();
    }

    const int g = lane >> 2, t4 = lane & 3;
#pragma unroll
    for (int mt = 0; mt < 2; ++mt) {
        int row = m0 + warp_m * 32 + mt * 16 + g;
#pragma unroll
        for (int nt = 0; nt < 8; ++nt) {
            int col = n0 + warp_n * 64 + nt * 8 + 2 * t4;
            float b0 = bias[col], b1 = bias[col + 1];
            float* d = acc[mt][nt];
            *(float2*)&Y[(size_t)row * DMODEL + col] = make_float2(d[0] + b0, d[1] + b1);
            *(float2*)&Y[(size_t)(row + 8) * DMODEL + col] = make_float2(d[2] + b0, d[3] + b1);
        }
    }
}

__global__ void __launch_bounds__(256, 1)
qkv_mma(const float* __restrict__ xq, const float* __restrict__ xk,
        const float* __restrict__ xv,
        const float* __restrict__ wq, const float* __restrict__ wk,
        const float* __restrict__ wv,
        const float* __restrict__ bq, const float* __restrict__ bk,
        const float* __restrict__ bv)
{
    int z = blockIdx.z;
    const float* X = (z == 0) ? xq : (z == 1) ? xk : xv;
    const float* W = (z == 0) ? wq : (z == 1) ? wk : wv;
    const float* bias = (z == 0) ? bq : (z == 1) ? bk : bv;
    float* Y = (z == 0) ? g_q : (z == 1) ? g_k : g_v;
    bf16x3_gemm(X, W, bias, Y);
}

__global__ void __launch_bounds__(256, 1)
out_mma(const float* __restrict__ Wo, const float* __restrict__ bo,
        float* __restrict__ Y)
{
    bf16x3_gemm(g_ctx, Wo, bo, Y);
}

// ============================================================================
// fused attention, 512 threads / 16 warps, warp tile 32x32 (4x4 warp grid)
//   + warp-level dead-tile skip for fully-OOB warp tiles (SEQ=196 vs 128 tiles)
// ============================================================================
// 512-thread staging: 2 float4 per thread
__device__ __forceinline__ void stage_store512(char* bp, const float4 pa[2],
                                               const float4 pb[2], int r_ld, int c4)
{
#pragma unroll
    for (int it = 0; it < 2; ++it) {
        uint32_t off = (uint32_t)(it * 64 + r_ld) * GSTRIDE + c4 * 8;
        uint2 hi, lo;
        split4(pa[it], hi, lo);
        *(uint2*)(bp + OFF_AHI + off) = hi;
        *(uint2*)(bp + OFF_ALO + off) = lo;
        split4(pb[it], hi, lo);
        *(uint2*)(bp + OFF_BHI + off) = hi;
        *(uint2*)(bp + OFF_BLO + off) = lo;
    }
}

// one 32-K chunk, 16-warp layout (warp tile 32x32)
__device__ __forceinline__ void mma_chunk512(uint32_t base, float acc[2][4][4],
                                             int warp_m, int warp_n, int sub, int i8)
{
#pragma unroll
    for (int ks = 0; ks < 2; ++ks) {
        const int kofs = ks * 16;
        uint32_t aHi[2][4], aLo[2][4];
#pragma unroll
        for (int mt = 0; mt < 2; ++mt) {
            int row = warp_m * 32 + mt * 16 + (sub & 1) * 8 + i8;
            int col = kofs + (sub >> 1) * 8;
            uint32_t ad = base + OFF_AHI + (uint32_t)row * GSTRIDE + col * 2;
            ldsm4(aHi[mt], ad);
            ldsm4(aLo[mt], ad + (OFF_ALO - OFF_AHI));
        }
#pragma unroll
        for (int ntp = 0; ntp < 2; ++ntp) {
            int nr = warp_n * 32 + ntp * 16 + (sub >> 1) * 8 + i8;
            int nc = kofs + (sub & 1) * 8;
            uint32_t bd = base + OFF_BHI + (uint32_t)nr * GSTRIDE + nc * 2;
            uint32_t bHi[4], bLo[4];
            ldsm4(bHi, bd);
            ldsm4(bLo, bd + (OFF_BLO - OFF_BHI));
#pragma unroll
            for (int mt = 0; mt < 2; ++mt) {
#pragma unroll
                for (int nh = 0; nh < 2; ++nh) {
                    float* d = acc[mt][ntp * 2 + nh];
                    mma16816(d, aHi[mt], &bHi[nh * 2]);
                    mma16816(d, aLo[mt], &bHi[nh * 2]);
                    mma16816(d, aHi[mt], &bLo[nh * 2]);
                }
            }
        }
    }
}

__global__ void __launch_bounds__(512, 1)
fused_attn()
{
    extern __shared__ __align__(16) char sm[];
    const uint32_t smb = smem_u32(sm);
    float* sS = (float*)(sm + 2 * BUFSZ);        // 128 x SSTRIDE fp32

    const int bh = blockIdx.y;
    const int b = bh >> 3, h = bh & 7;
    const int m0 = blockIdx.x * 128;
    const float* Q  = g_q + (size_t)b * SEQ * DMODEL + h * DK;
    const float* Kp = g_k + (size_t)b * SEQ * DMODEL + h * DK;
    const float* LW = g_logw + (size_t)bh * SEQ * SEQ;
    const float* Vt = g_vT + (size_t)bh * DK * SEQ;

    const int tid = threadIdx.x;
    const int lane = tid & 31, w = tid >> 5;     // w: 0..15
    const int warp_m = w & 3, warp_n = w >> 2;   // 4 x 4 warp grid
    const int r_ld = tid >> 3, c4 = tid & 7;     // r_ld: 0..63
    const int sub = lane >> 3, i8 = lane & 7;
    const int g = lane >> 2, t4 = lane & 3;
    const float4 z4 = make_float4(0.f, 0.f, 0.f, 0.f);

    // warp-tile liveness: a 32-row/col warp tile fully beyond SEQ does no MMA work
    const bool m_live = (m0 + warp_m * 32) < SEQ;

    float acc[2][4][4];
    float4 pa[2], pb[2];

    // ======== Phase A: S = Q K^T * scale + logw (two 128x128 n-halves) ========
    const float scale = 0.08838834764831845f;   // 1/sqrt(128)
#pragma unroll 1
    for (int nt2 = 0; nt2 < 2; ++nt2) {
        const int n0 = nt2 * 128;
        const bool live = m_live && ((n0 + warp_n * 32) < SEQ);
#pragma unroll
        for (int mt = 0; mt < 2; mt++)
#pragma unroll
            for (int nt = 0; nt < 4; nt++)
#pragma unroll
                for (int e = 0; e < 4; e++) acc[mt][nt][e] = 0.f;

        {
            int gk = c4 * 4;
#pragma unroll
            for (int it = 0; it < 2; ++it) {
                int am = m0 + it * 64 + r_ld;
                int bn = n0 + it * 64 + r_ld;
                pa[it] = (am < SEQ) ? *(const float4*)(Q + (size_t)am * DMODEL + gk) : z4;
                pb[it] = (bn < SEQ) ? *(const float4*)(Kp + (size_t)bn * DMODEL + gk) : z4;
            }
            stage_store512(sm, pa, pb, r_ld, c4);
        }
        __syncthreads();

        for (int c = 0; c < 4; ++c) {          // DK=128 -> 4 chunks
            if (c + 1 < 4) {
                int gk = (c + 1) * KCHUNK + c4 * 4;
#pragma unroll
                for (int it = 0; it < 2; ++it) {
                    int am = m0 + it * 64 + r_ld;
                    int bn = n0 + it * 64 + r_ld;
                    pa[it] = (am < SEQ) ? *(const float4*)(Q + (size_t)am * DMODEL + gk) : z4;
                    pb[it] = (bn < SEQ) ? *(const float4*)(Kp + (size_t)bn * DMODEL + gk) : z4;
                }
            }
            if (live)
                mma_chunk512(smb + (uint32_t)(c & 1) * BUFSZ, acc, warp_m, warp_n, sub, i8);
            if (c + 1 < 4)
                stage_store512(sm + ((c + 1) & 1) * BUFSZ, pa, pb, r_ld, c4);
            __syncthreads();
        }

        // epilogue -> sS (+logw)
#pragma unroll
        for (int mt = 0; mt < 2; ++mt) {
            int rl = warp_m * 32 + mt * 16 + g;        // local row 0..127
            int m = m0 + rl;
#pragma unroll
            for (int nt = 0; nt < 4; ++nt) {
                int col = n0 + warp_n * 32 + nt * 8 + 2 * t4;
                float* d = acc[mt][nt];
                if (col < SEQ) {
                    bool mok = (m < SEQ);
                    float l0 = mok ? LW[(size_t)m * SEQ + col] : 0.f;
                    float l1 = mok ? LW[(size_t)m * SEQ + col + 1] : 0.f;
                    *(float2*)&sS[(size_t)rl * SSTRIDE + col] =
                        make_float2(fmaf(d[0], scale, l0), fmaf(d[1], scale, l1));
                    bool m8 = (m + 8 < SEQ);
                    float l2 = m8 ? LW[(size_t)(m + 8) * SEQ + col] : 0.f;
                    float l3 = m8 ? LW[(size_t)(m + 8) * SEQ + col + 1] : 0.f;
                    *(float2*)&sS[(size_t)(rl + 8) * SSTRIDE + col] =
                        make_float2(fmaf(d[2], scale, l2), fmaf(d[3], scale, l3));
                }
            }
        }
        __syncthreads();
    }

    // ======== Phase B: softmax rows in SMEM (16 warps x 8 rows) ========
    {
#pragma unroll 1
        for (int j = 0; j < 8; ++j) {
            int r = w * 8 + j;
            float* row = sS + (size_t)r * SSTRIDE;
            float x[7];
            float mx = -1e30f;
#pragma unroll
            for (int i = 0; i < 7; ++i) {
                int cidx = lane + i * 32;
                x[i] = (cidx < SEQ) ? row[cidx] : -1e30f;
                mx = fmaxf(mx, x[i]);
            }
#pragma unroll
            for (int o = 16; o > 0; o >>= 1) mx = fmaxf(mx, __shfl_xor_sync(0xffffffffu, mx, o));
            float sum = 0.f;
#pragma unroll
            for (int i = 0; i < 7; ++i) {
                x[i] = expf(x[i] - mx);
                sum += x[i];
            }
#pragma unroll
            for (int o = 16; o > 0; o >>= 1) sum += __shfl_xor_sync(0xffffffffu, sum, o);
            float inv = 1.0f / sum;
#pragma unroll
            for (int i = 0; i < 7; ++i) {
                int cidx = lane + i * 32;
                if (cidx < SEQ) row[cidx] = x[i] * inv;
            }
            if (lane < 28) row[SEQ + lane] = 0.f;     // zero pad cols 196..223
        }
    }
    __syncthreads();

    // ======== Phase C: ctx = P @ V^T (output 128x128, n = DK dense) ========
#pragma unroll
    for (int mt = 0; mt < 2; mt++)
#pragma unroll
        for (int nt = 0; nt < 4; nt++)
#pragma unroll
            for (int e = 0; e < 4; e++) acc[mt][nt][e] = 0.f;

    const int nchunkC = 7;                        // ceil(196/32)
    {
        int gk = c4 * 4;
#pragma unroll
        for (int it = 0; it < 2; ++it) {
            int rr = it * 64 + r_ld;
            pa[it] = *(const float4*)(sS + (size_t)rr * SSTRIDE + gk);
            pb[it] = *(const float4*)(Vt + (size_t)rr * SEQ + gk);
        }
        stage_store512(sm, pa, pb, r_ld, c4);
    }
    __syncthreads();

    for (int c = 0; c < nchunkC; ++c) {
        if (c + 1 < nchunkC) {
            int gk = (c + 1) * KCHUNK + c4 * 4;
            bool kok = gk < SEQ;
#pragma unroll
            for (int it = 0; it < 2; ++it) {
                int rr = it * 64 + r_ld;
                pa[it] = *(const float4*)(sS + (size_t)rr * SSTRIDE + gk);   // pad zeroed
                pb[it] = kok ? *(const float4*)(Vt + (size_t)rr * SEQ + gk) : z4;
            }
        }
        if (m_live)
            mma_chunk512(smb + (uint32_t)(c & 1) * BUFSZ, acc, warp_m, warp_n, sub, i8);
        if (c + 1 < nchunkC)
            stage_store512(sm + ((c + 1) & 1) * BUFSZ, pa, pb, r_ld, c4);
        __syncthreads();
    }

    // epilogue -> g_ctx
    float* C = g_ctx + (size_t)b * SEQ * DMODEL + h * DK;
#pragma unroll
    for (int mt = 0; mt < 2; ++mt) {
        int m = m0 + warp_m * 32 + mt * 16 + g;
#pragma unroll
        for (int nt = 0; nt < 4; ++nt) {
            int col = warp_n * 32 + nt * 8 + 2 * t4;
            float* d = acc[mt][nt];
            if (m < SEQ)
                *(float2*)(C + (size_t)m * DMODEL + col) = make_float2(d[0], d[1]);
            if (m + 8 < SEQ)
                *(float2*)(C + (size_t)(m + 8) * DMODEL + col) = make_float2(d[2], d[3]);
        }
    }
}

// ---------------- V transpose: g_vT[bh][n][k] = g_v[b][k][h*DK+n] ----------------
__global__ void vT_kernel()
{
    __shared__ float t[32][33];
    int bh = blockIdx.z;
    int b = bh >> 3, h = bh & 7;
    int k0 = blockIdx.x * 32, n0 = blockIdx.y * 32;
    int tx = threadIdx.x, ty = threadIdx.y;   // 32 x 8
#pragma unroll
    for (int j = 0; j < 4; ++j) {
        int k = k0 + ty + j * 8;
        t[ty + j * 8][tx] = (k < SEQ)
            ? g_v[((size_t)b * SEQ + k) * DMODEL + h * DK + n0 + tx] : 0.f;
    }
    __syncthreads();
#pragma unroll
    for (int j = 0; j < 4; ++j) {
        int n = n0 + ty + j * 8;
        int k = k0 + tx;
        if (k < SEQ)
            g_vT[(size_t)bh * DK * SEQ + (size_t)n * SEQ + k] = t[tx][ty + j * 8];
    }
}

// ---------------- geometry embedding -> logw[b,h,n,m] ----------------
__global__ void logw_kernel(const float* __restrict__ boxes,
                            const float* __restrict__ WGw,
                            const float* __restrict__ WGb)
{
    __shared__ float sW[8][64];
    __shared__ float sB[8];
    __shared__ float sbn[4];
    int t = threadIdx.x;
    int b = blockIdx.x / SEQ;
    int n = blockIdx.x % SEQ;

    for (int i = t; i < 512; i += blockDim.x) sW[i >> 6][i & 63] = WGw[i];
    if (t < 8) sB[t] = WGb[t];
    if (t == 0) {
        const float* bp = boxes + ((size_t)b * SEQ + n) * 4;
        float xmn = bp[0], ymn = bp[1], xmx = bp[2], ymx = bp[3];
        sbn[0] = (xmn + xmx) * 0.5f;
        sbn[1] = (ymn + ymx) * 0.5f;
        sbn[2] = (xmx - xmn) + 1.0f;
        sbn[3] = (ymx - ymn) + 1.0f;
    }
    __syncthreads();

    int m = t;
    if (m >= SEQ) return;

    const float* bm = boxes + ((size_t)b * SEQ + m) * 4;
    float xmn = bm[0], ymn = bm[1], xmx = bm[2], ymx = bm[3];
    float cxm = (xmn + xmx) * 0.5f, cym = (ymn + ymx) * 0.5f;
    float wm = (xmx - xmn) + 1.0f, hm = (ymx - ymn) + 1.0f;
    float cxn = sbn[0], cyn = sbn[1], wn = sbn[2], hn = sbn[3];

    float pos[4];
    pos[0] = logf(fmaxf(fabsf((cxn - cxm) / wn), 1e-3f));
    pos[1] = logf(fmaxf(fabsf((cyn - cym) / hn), 1e-3f));
    pos[2] = logf(wn / wm);
    pos[3] = logf(hn / hm);

    float acc[8];
#pragma unroll
    for (int h = 0; h < 8; h++) acc[h] = sB[h];

#pragma unroll
    for (int c = 0; c < 4; c++) {
        float p = 100.0f * pos[c];
#pragma unroll
        for (int j = 0; j < 8; j++) {
            float s, co;
            __sincosf(p * c_dim[j], &s, &co);
            int f = c * 8 + j;
#pragma unroll
            for (int h = 0; h < 8; h++)
                acc[h] += s * sW[h][f] + co * sW[h][f + 32];
        }
    }

    size_t base = ((size_t)b * HEADS) * SEQ * SEQ + (size_t)n * SEQ + m;
#pragma unroll
    for (int h = 0; h < 8; h++) {
        float wg = fmaxf(acc[h], 1e-6f);
        g_logw[base + (size_t)h * SEQ * SEQ] = logf(wg);
    }
}

// ---------------- launch ----------------
extern "C" void kernel_launch(void* const* d_in, const int* in_sizes, int n_in,
                              void* d_out, int out_size)
{
    const float* xq  = (const float*)d_in[0];
    const float* xk  = (const float*)d_in[1];
    const float* xv  = (const float*)d_in[2];
    const float* box = (const float*)d_in[3];
    const float* Wq  = (const float*)d_in[4];
    const float* bq  = (const float*)d_in[5];
    const float* Wk  = (const float*)d_in[6];
    const float* bk  = (const float*)d_in[7];
    const float* Wv  = (const float*)d_in[8];
    const float* bv  = (const float*)d_in[9];
    const float* Wo  = (const float*)d_in[10];
    const float* bo  = (const float*)d_in[11];
    const float* WGw = (const float*)d_in[12];
    const float* WGb = (const float*)d_in[13];
    float* out = (float*)d_out;

    cudaFuncSetAttribute(qkv_mma,    cudaFuncAttributeMaxDynamicSharedMemorySize, SMEMSZ);
    cudaFuncSetAttribute(out_mma,    cudaFuncAttributeMaxDynamicSharedMemorySize, SMEMSZ);
    cudaFuncSetAttribute(fused_attn, cudaFuncAttributeMaxDynamicSharedMemorySize, SMEM_FUSED);

    // 1) Q/K/V projections (bf16x3 MMA, 256 threads — R7 config)
    qkv_mma<<<dim3(DMODEL / 128, MROWS / 128, 3), 256, SMEMSZ>>>(
        xq, xk, xv, Wq, Wk, Wv, bq, bk, bv);

    // 2) transpose V per head
    vT_kernel<<<dim3(7, 4, BATCH * HEADS), dim3(32, 8)>>>();

    // 3) geometry relation log-weights
    logw_kernel<<<BATCH * SEQ, 224>>>(box, WGw, WGb);

    // 4) fused: S = QK^T/sqrt(dk)+logw -> softmax -> P@V  (512 threads, dead-tile skip)
    fused_attn<<<dim3(2, BATCH * HEADS), 512, SMEM_FUSED>>>();

    // 5) output projection into d_out (256 threads — R7 config)
    out_mma<<<dim3(DMODEL / 128, MROWS / 128, 1), 256, SMEMSZ>>>(Wo, bo, out);
}